// round 1
// baseline (speedup 1.0000x reference)
#include <cuda_runtime.h>

// CumulantSOAP: per-column mean/var of X (200000 x 576 f32) -> (cum - mu) @ W (1728x4) -> 4 floats.
// Single pass over X (S1, S2), mom1 treated as 0 (pure fp rounding residual in reference,
// ~1e-7 relative contribution). Deterministic 3-kernel tree reduction (no float atomics).

#define NROWS   200000
#define PCOLS   576          // columns of X
#define PV      144          // PCOLS / 4 (float4 groups)
#define GRID1   296          // stage-1 blocks (2 CTAs / SM on 148 SMs)
#define K2B     72           // stage-2 blocks (8 columns each)

// Scratch (allocation-free rule: __device__ globals)
__device__ float g_s1[PCOLS * GRID1];   // per (col, block) partial sum x
__device__ float g_s2[PCOLS * GRID1];   // per (col, block) partial sum x^2
__device__ float g_part[K2B * 4];       // per stage-2 block partial 4-vector

// -------------------- Stage 1: column sums over X --------------------
__global__ __launch_bounds__(576) void k1_colsums(const float* __restrict__ X) {
    const int tx = threadIdx.x;   // 0..143 : float4 column group
    const int ty = threadIdx.y;   // 0..3   : row phase
    const float4* __restrict__ Xv = reinterpret_cast<const float4*>(X);

    float s1x = 0.f, s1y = 0.f, s1z = 0.f, s1w = 0.f;
    float s2x = 0.f, s2y = 0.f, s2z = 0.f, s2w = 0.f;

    int r = blockIdx.x * 4 + ty;
    const int rstride = gridDim.x * 4;
    const float4* __restrict__ p = Xv + (size_t)r * PV + tx;
    const size_t pstride = (size_t)rstride * PV;

    #pragma unroll 4
    for (; r < NROWS; r += rstride, p += pstride) {
        float4 v = __ldg(p);
        s1x += v.x; s1y += v.y; s1z += v.z; s1w += v.w;
        s2x = fmaf(v.x, v.x, s2x);
        s2y = fmaf(v.y, v.y, s2y);
        s2z = fmaf(v.z, v.z, s2z);
        s2w = fmaf(v.w, v.w, s2w);
    }

    // reduce over the 4 row phases via smem
    __shared__ float red[4][PV][8];   // 18432 B
    float* slot = red[ty][tx];
    slot[0] = s1x; slot[1] = s1y; slot[2] = s1z; slot[3] = s1w;
    slot[4] = s2x; slot[5] = s2y; slot[6] = s2z; slot[7] = s2w;
    __syncthreads();

    if (ty == 0) {
        #pragma unroll
        for (int c = 0; c < 4; c++) {
            float a = red[0][tx][c]     + red[1][tx][c]     + red[2][tx][c]     + red[3][tx][c];
            float b = red[0][tx][4 + c] + red[1][tx][4 + c] + red[2][tx][4 + c] + red[3][tx][4 + c];
            int col = 4 * tx + c;
            g_s1[col * GRID1 + blockIdx.x] = a;
            g_s2[col * GRID1 + blockIdx.x] = b;
        }
    }
}

// -------------------- Stage 2: finish cumulants, fold projection --------------------
__global__ __launch_bounds__(256) void k2_project(const float* __restrict__ mu,
                                                  const float* __restrict__ W) {
    const int warp = threadIdx.x >> 5;   // 0..7
    const int lane = threadIdx.x & 31;
    const int col  = blockIdx.x * 8 + warp;   // 0..575

    float s1 = 0.f, s2 = 0.f;
    for (int i = lane; i < GRID1; i += 32) {
        s1 += g_s1[col * GRID1 + i];
        s2 += g_s2[col * GRID1 + i];
    }
    #pragma unroll
    for (int off = 16; off > 0; off >>= 1) {
        s1 += __shfl_down_sync(0xFFFFFFFFu, s1, off);
        s2 += __shfl_down_sync(0xFFFFFFFFu, s2, off);
    }

    __shared__ float wout[8][4];
    if (lane == 0) {
        const float invN = 1.0f / (float)NROWS;
        float m    = s1 * invN;
        float mom2 = fmaf(-m, m, s2 * invN);   // E[x^2] - m^2
        int base = 3 * col;
        float c0 = m - mu[base];
        float c1 =   - mu[base + 1];           // mom1 ~ 0
        float c2 = mom2 - mu[base + 2];
        #pragma unroll
        for (int k = 0; k < 4; k++) {
            wout[warp][k] = c0 * W[(base    ) * 4 + k]
                          + c1 * W[(base + 1) * 4 + k]
                          + c2 * W[(base + 2) * 4 + k];
        }
    }
    __syncthreads();

    if (threadIdx.x < 4) {
        float acc = 0.f;
        #pragma unroll
        for (int w = 0; w < 8; w++) acc += wout[w][threadIdx.x];
        g_part[blockIdx.x * 4 + threadIdx.x] = acc;
    }
}

// -------------------- Stage 3: final 72x4 -> 4 --------------------
__global__ __launch_bounds__(128) void k3_final(float* __restrict__ out) {
    const int k    = threadIdx.x >> 5;   // warp -> output index
    const int lane = threadIdx.x & 31;

    float acc = 0.f;
    for (int i = lane; i < K2B; i += 32) acc += g_part[i * 4 + k];
    #pragma unroll
    for (int off = 16; off > 0; off >>= 1)
        acc += __shfl_down_sync(0xFFFFFFFFu, acc, off);

    if (lane == 0) out[k] = acc;
}

extern "C" void kernel_launch(void* const* d_in, const int* in_sizes, int n_in,
                              void* d_out, int out_size) {
    const float* X  = (const float*)d_in[0];
    const float* mu = (const float*)d_in[1];
    const float* W  = (const float*)d_in[2];
    float* out = (float*)d_out;

    k1_colsums<<<GRID1, dim3(PV, 4)>>>(X);
    k2_project<<<K2B, 256>>>(mu, W);
    k3_final<<<1, 128>>>(out);
}

// round 2
// speedup vs baseline: 1.2994x; 1.2994x over previous
#include <cuda_runtime.h>

// CumulantSOAP: per-column mean/var of X (200000 x 576 f32) -> (cum - mu) @ W (1728x4) -> 4 floats.
// Single pass (S1, S2); mom1 treated as 0 (pure fp rounding residual). Deterministic 3-stage tree.
//
// R2: K1 rebuilt for latency hiding: 288-thread blocks (column group = tid%144 invariant under
// stride 740*288), explicit 4-way independent float4 loads (MLP=4 guaranteed), grid 740
// (5 blocks x 9 warps = 45 warps/SM at ~40 regs), __ldcs streaming loads.

#define NROWS   200000
#define PCOLS   576
#define PV      144                       // float4 groups per row
#define TOTALV  ((size_t)NROWS * PV)      // 28,800,000 float4
#define BLK1    288
#define G1      740
#define K2B     72

__device__ float g_s1[(size_t)G1 * PCOLS];   // [block][col] partial sum x
__device__ float g_s2[(size_t)G1 * PCOLS];   // [block][col] partial sum x^2
__device__ float g_part[K2B * 4];

// -------------------- Stage 1 --------------------
__global__ __launch_bounds__(BLK1) void k1_colsums(const float* __restrict__ X) {
    const float4* __restrict__ Xv = reinterpret_cast<const float4*>(X);
    const int tid = threadIdx.x;

    float s1x = 0.f, s1y = 0.f, s1z = 0.f, s1w = 0.f;
    float s2x = 0.f, s2y = 0.f, s2z = 0.f, s2w = 0.f;

    size_t i = (size_t)blockIdx.x * BLK1 + tid;
    const size_t stride = (size_t)G1 * BLK1;   // 213120, divisible by 144

    // main: 4 independent loads in flight per thread
    for (; i + 3 * stride < TOTALV; i += 4 * stride) {
        float4 a = __ldcs(Xv + i);
        float4 b = __ldcs(Xv + i + stride);
        float4 c = __ldcs(Xv + i + 2 * stride);
        float4 d = __ldcs(Xv + i + 3 * stride);

        s1x += a.x; s1y += a.y; s1z += a.z; s1w += a.w;
        s2x = fmaf(a.x, a.x, s2x); s2y = fmaf(a.y, a.y, s2y);
        s2z = fmaf(a.z, a.z, s2z); s2w = fmaf(a.w, a.w, s2w);

        s1x += b.x; s1y += b.y; s1z += b.z; s1w += b.w;
        s2x = fmaf(b.x, b.x, s2x); s2y = fmaf(b.y, b.y, s2y);
        s2z = fmaf(b.z, b.z, s2z); s2w = fmaf(b.w, b.w, s2w);

        s1x += c.x; s1y += c.y; s1z += c.z; s1w += c.w;
        s2x = fmaf(c.x, c.x, s2x); s2y = fmaf(c.y, c.y, s2y);
        s2z = fmaf(c.z, c.z, s2z); s2w = fmaf(c.w, c.w, s2w);

        s1x += d.x; s1y += d.y; s1z += d.z; s1w += d.w;
        s2x = fmaf(d.x, d.x, s2x); s2y = fmaf(d.y, d.y, s2y);
        s2z = fmaf(d.z, d.z, s2z); s2w = fmaf(d.w, d.w, s2w);
    }
    // remainder
    for (; i < TOTALV; i += stride) {
        float4 a = __ldcs(Xv + i);
        s1x += a.x; s1y += a.y; s1z += a.z; s1w += a.w;
        s2x = fmaf(a.x, a.x, s2x); s2y = fmaf(a.y, a.y, s2y);
        s2z = fmaf(a.z, a.z, s2z); s2w = fmaf(a.w, a.w, s2w);
    }

    // pair-reduce: tid and tid+144 share the same column group (tid % 144)
    __shared__ float red[PV][8];
    if (tid >= PV) {
        float* r = red[tid - PV];
        r[0] = s1x; r[1] = s1y; r[2] = s1z; r[3] = s1w;
        r[4] = s2x; r[5] = s2y; r[6] = s2z; r[7] = s2w;
    }
    __syncthreads();
    if (tid < PV) {
        const float* r = red[tid];
        float4 o1 = make_float4(s1x + r[0], s1y + r[1], s1z + r[2], s1w + r[3]);
        float4 o2 = make_float4(s2x + r[4], s2y + r[5], s2z + r[6], s2w + r[7]);
        float4* d1 = reinterpret_cast<float4*>(g_s1) + (size_t)blockIdx.x * PV + tid;
        float4* d2 = reinterpret_cast<float4*>(g_s2) + (size_t)blockIdx.x * PV + tid;
        *d1 = o1;
        *d2 = o2;
    }
}

// -------------------- Stage 2: reduce over blocks, fold projection --------------------
__global__ __launch_bounds__(256) void k2_project(const float* __restrict__ mu,
                                                  const float* __restrict__ W) {
    const int warp = threadIdx.x >> 5;
    const int lane = threadIdx.x & 31;
    const int col  = blockIdx.x * 8 + warp;   // 0..575

    float s1 = 0.f, s2 = 0.f;
    for (int b = lane; b < G1; b += 32) {
        s1 += g_s1[(size_t)b * PCOLS + col];
        s2 += g_s2[(size_t)b * PCOLS + col];
    }
    #pragma unroll
    for (int off = 16; off > 0; off >>= 1) {
        s1 += __shfl_down_sync(0xFFFFFFFFu, s1, off);
        s2 += __shfl_down_sync(0xFFFFFFFFu, s2, off);
    }

    __shared__ float wout[8][4];
    if (lane == 0) {
        const float invN = 1.0f / (float)NROWS;
        float m    = s1 * invN;
        float mom2 = fmaf(-m, m, s2 * invN);   // E[x^2] - m^2
        int base = 3 * col;
        float c0 = m - mu[base];
        float c1 =   - mu[base + 1];           // mom1 ~ 0
        float c2 = mom2 - mu[base + 2];
        #pragma unroll
        for (int k = 0; k < 4; k++) {
            wout[warp][k] = c0 * W[(base    ) * 4 + k]
                          + c1 * W[(base + 1) * 4 + k]
                          + c2 * W[(base + 2) * 4 + k];
        }
    }
    __syncthreads();

    if (threadIdx.x < 4) {
        float acc = 0.f;
        #pragma unroll
        for (int w = 0; w < 8; w++) acc += wout[w][threadIdx.x];
        g_part[blockIdx.x * 4 + threadIdx.x] = acc;
    }
}

// -------------------- Stage 3 --------------------
__global__ __launch_bounds__(128) void k3_final(float* __restrict__ out) {
    const int k    = threadIdx.x >> 5;
    const int lane = threadIdx.x & 31;

    float acc = 0.f;
    for (int i = lane; i < K2B; i += 32) acc += g_part[i * 4 + k];
    #pragma unroll
    for (int off = 16; off > 0; off >>= 1)
        acc += __shfl_down_sync(0xFFFFFFFFu, acc, off);

    if (lane == 0) out[k] = acc;
}

extern "C" void kernel_launch(void* const* d_in, const int* in_sizes, int n_in,
                              void* d_out, int out_size) {
    const float* X  = (const float*)d_in[0];
    const float* mu = (const float*)d_in[1];
    const float* W  = (const float*)d_in[2];
    float* out = (float*)d_out;

    k1_colsums<<<G1, BLK1>>>(X);
    k2_project<<<K2B, 256>>>(mu, W);
    k3_final<<<1, 128>>>(out);
}

// round 4
// speedup vs baseline: 1.3247x; 1.0195x over previous
#include <cuda_runtime.h>

// CumulantSOAP: per-column mean/var of X (200000 x 576 f32) -> (cum - mu) @ W (1728x4) -> 4 floats.
// Single pass (S1, S2); mom1 treated as 0 (pure fp rounding residual). Deterministic.
//
// R3: K2+K3 fused via last-block pattern (int atomic counter, fixed summation order ->
// deterministic; counter self-resets). K2 widened to 144 blocks (warp per column).
// K1 unchanged from R2 (measured at DRAM wall: 6.63 TB/s, 83.7%).

#define NROWS   200000
#define PCOLS   576
#define PV      144                       // float4 groups per row
#define TOTALV  ((size_t)NROWS * PV)      // 28,800,000 float4
#define BLK1    288
#define G1      740
#define K2B     144

__device__ float g_s1[(size_t)G1 * PCOLS];   // [block][col] partial sum x
__device__ float g_s2[(size_t)G1 * PCOLS];   // [block][col] partial sum x^2
__device__ float g_part[K2B * 4];
__device__ int   g_count = 0;

// -------------------- Stage 1 --------------------
__global__ __launch_bounds__(BLK1) void k1_colsums(const float* __restrict__ X) {
    const float4* __restrict__ Xv = reinterpret_cast<const float4*>(X);
    const int tid = threadIdx.x;

    float s1x = 0.f, s1y = 0.f, s1z = 0.f, s1w = 0.f;
    float s2x = 0.f, s2y = 0.f, s2z = 0.f, s2w = 0.f;

    size_t i = (size_t)blockIdx.x * BLK1 + tid;
    const size_t stride = (size_t)G1 * BLK1;   // 213120, divisible by 144

    for (; i + 3 * stride < TOTALV; i += 4 * stride) {
        float4 a = __ldcs(Xv + i);
        float4 b = __ldcs(Xv + i + stride);
        float4 c = __ldcs(Xv + i + 2 * stride);
        float4 d = __ldcs(Xv + i + 3 * stride);

        s1x += a.x; s1y += a.y; s1z += a.z; s1w += a.w;
        s2x = fmaf(a.x, a.x, s2x); s2y = fmaf(a.y, a.y, s2y);
        s2z = fmaf(a.z, a.z, s2z); s2w = fmaf(a.w, a.w, s2w);

        s1x += b.x; s1y += b.y; s1z += b.z; s1w += b.w;
        s2x = fmaf(b.x, b.x, s2x); s2y = fmaf(b.y, b.y, s2y);
        s2z = fmaf(b.z, b.z, s2z); s2w = fmaf(b.w, b.w, s2w);

        s1x += c.x; s1y += c.y; s1z += c.z; s1w += c.w;
        s2x = fmaf(c.x, c.x, s2x); s2y = fmaf(c.y, c.y, s2y);
        s2z = fmaf(c.z, c.z, s2z); s2w = fmaf(c.w, c.w, s2w);

        s1x += d.x; s1y += d.y; s1z += d.z; s1w += d.w;
        s2x = fmaf(d.x, d.x, s2x); s2y = fmaf(d.y, d.y, s2y);
        s2z = fmaf(d.z, d.z, s2z); s2w = fmaf(d.w, d.w, s2w);
    }
    for (; i < TOTALV; i += stride) {
        float4 a = __ldcs(Xv + i);
        s1x += a.x; s1y += a.y; s1z += a.z; s1w += a.w;
        s2x = fmaf(a.x, a.x, s2x); s2y = fmaf(a.y, a.y, s2y);
        s2z = fmaf(a.z, a.z, s2z); s2w = fmaf(a.w, a.w, s2w);
    }

    // pair-reduce: tid and tid+144 share the same column group (tid % 144)
    __shared__ float red[PV][8];
    if (tid >= PV) {
        float* r = red[tid - PV];
        r[0] = s1x; r[1] = s1y; r[2] = s1z; r[3] = s1w;
        r[4] = s2x; r[5] = s2y; r[6] = s2z; r[7] = s2w;
    }
    __syncthreads();
    if (tid < PV) {
        const float* r = red[tid];
        float4 o1 = make_float4(s1x + r[0], s1y + r[1], s1z + r[2], s1w + r[3]);
        float4 o2 = make_float4(s2x + r[4], s2y + r[5], s2z + r[6], s2w + r[7]);
        float4* d1 = reinterpret_cast<float4*>(g_s1) + (size_t)blockIdx.x * PV + tid;
        float4* d2 = reinterpret_cast<float4*>(g_s2) + (size_t)blockIdx.x * PV + tid;
        *d1 = o1;
        *d2 = o2;
    }
}

// -------- Stage 2 (fused final): reduce over blocks, fold projection, last block finishes --------
__global__ __launch_bounds__(128) void k2_project(const float* __restrict__ mu,
                                                  const float* __restrict__ W,
                                                  float* __restrict__ out) {
    const int warp = threadIdx.x >> 5;          // 0..3
    const int lane = threadIdx.x & 31;
    const int col  = blockIdx.x * 4 + warp;     // 0..575

    float s1 = 0.f, s2 = 0.f;
    for (int b = lane; b < G1; b += 32) {
        s1 += g_s1[(size_t)b * PCOLS + col];
        s2 += g_s2[(size_t)b * PCOLS + col];
    }
    #pragma unroll
    for (int off = 16; off > 0; off >>= 1) {
        s1 += __shfl_down_sync(0xFFFFFFFFu, s1, off);
        s2 += __shfl_down_sync(0xFFFFFFFFu, s2, off);
    }

    __shared__ float wout[4][4];
    __shared__ int   s_last;
    if (lane == 0) {
        const float invN = 1.0f / (float)NROWS;
        float m    = s1 * invN;
        float mom2 = fmaf(-m, m, s2 * invN);    // E[x^2] - m^2
        int base = 3 * col;
        float c0 = m - mu[base];
        float c1 =   - mu[base + 1];            // mom1 ~ 0
        float c2 = mom2 - mu[base + 2];
        #pragma unroll
        for (int k = 0; k < 4; k++) {
            wout[warp][k] = c0 * W[(base    ) * 4 + k]
                          + c1 * W[(base + 1) * 4 + k]
                          + c2 * W[(base + 2) * 4 + k];
        }
    }
    __syncthreads();

    if (threadIdx.x < 4) {
        float acc = wout[0][threadIdx.x] + wout[1][threadIdx.x]
                  + wout[2][threadIdx.x] + wout[3][threadIdx.x];
        g_part[blockIdx.x * 4 + threadIdx.x] = acc;
    }
    __syncthreads();
    __threadfence();
    if (threadIdx.x == 0)
        s_last = (atomicAdd(&g_count, 1) == K2B - 1);
    __syncthreads();

    if (s_last) {
        __threadfence();
        if (threadIdx.x < 4) {
            volatile float* gp = g_part;
            float acc = 0.f;
            for (int i = 0; i < K2B; i++) acc += gp[i * 4 + threadIdx.x];
            out[threadIdx.x] = acc;
        }
        if (threadIdx.x == 0) g_count = 0;   // reset for next graph replay
    }
}

extern "C" void kernel_launch(void* const* d_in, const int* in_sizes, int n_in,
                              void* d_out, int out_size) {
    const float* X  = (const float*)d_in[0];
    const float* mu = (const float*)d_in[1];
    const float* W  = (const float*)d_in[2];
    float* out = (float*)d_out;

    k1_colsums<<<G1, BLK1>>>(X);
    k2_project<<<K2B, 128>>>(mu, W, out);
}